// round 2
// baseline (speedup 1.0000x reference)
#include <cuda_runtime.h>

#define TILE_E   32
#define THREADS  384
#define HTOT     384      // 64 structural + 192 chemical + 128 combined
#define KTOT     896      // 128 structural + 768 chemical
#define ROWPAD   36       // floats per k-row in smem (32 edges + 4 pad, 144B)

// Packed unified weights (zero-padded block structure), built per launch.
__device__ float g_W[KTOT * HTOT];   // [k][j] row-major
__device__ float g_b1[HTOT];
__device__ float g_w2[HTOT];

__global__ void pack_kernel(
    const float* __restrict__ sw1, const float* __restrict__ sb1, const float* __restrict__ sw2,
    const float* __restrict__ cw1, const float* __restrict__ cb1, const float* __restrict__ cw2,
    const float* __restrict__ mw1, const float* __restrict__ mb1, const float* __restrict__ mw2)
{
    int idx = blockIdx.x * blockDim.x + threadIdx.x;
    if (idx < KTOT * HTOT) {
        int k = idx / HTOT;
        int j = idx - k * HTOT;
        float v = 0.f;
        if (j < 64) {
            if (k < 128) v = sw1[k * 64 + j];                 // structural: K=128, H=64
        } else if (j < 256) {
            if (k >= 128) v = cw1[(k - 128) * 192 + (j - 64)]; // chemical: K=768, H=192
        } else {
            v = mw1[k * 128 + (j - 256)];                      // combined: K=896, H=128
        }
        g_W[k * HTOT + j] = v;
    } else if (idx < KTOT * HTOT + HTOT) {
        int j = idx - KTOT * HTOT;
        float b, w;
        if (j < 64)       { b = sb1[j];       w = sw2[j]; }
        else if (j < 256) { b = cb1[j - 64];  w = cw2[j - 64]; }
        else              { b = mb1[j - 256]; w = mw2[j - 256]; }
        g_b1[j] = b;
        g_w2[j] = w;
    }
}

// ---- packed f32x2 helpers (PTX-only path on sm_103a) ----
__device__ __forceinline__ unsigned long long pk2(float x, float y) {
    unsigned long long r;
    asm("mov.b64 %0, {%1, %2};" : "=l"(r) : "f"(x), "f"(y));
    return r;
}
__device__ __forceinline__ void fma2(unsigned long long& d, unsigned long long a, unsigned long long b) {
    asm("fma.rn.f32x2 %0, %1, %2, %0;" : "+l"(d) : "l"(a), "l"(b));
}
__device__ __forceinline__ float2 upk2(unsigned long long v) {
    float2 f;
    asm("mov.b64 {%0, %1}, %2;" : "=f"(f.x), "=f"(f.y) : "l"(v));
    return f;
}

struct Meta {
    int   srcs[TILE_E];
    int   dsts[TILE_E];
    float bothv[TILE_E];
    float scores[3][TILE_E];
};

__global__ void __launch_bounds__(THREADS)
decoder_kernel(
    const float* __restrict__ z, const float* __restrict__ chem,
    const int*   __restrict__ edge,   // int32! (JAX x64 disabled)
    const int*   __restrict__ mask,
    const float* __restrict__ sb2, const float* __restrict__ cb2,
    const float* __restrict__ mb2, const float* __restrict__ pw,
    float* __restrict__ out, int E)
{
    extern __shared__ char smem_raw[];
    float* S = reinterpret_cast<float*>(smem_raw);                   // [KTOT][ROWPAD]
    Meta*  M = reinterpret_cast<Meta*>(smem_raw + KTOT * ROWPAD * 4);

    const int tid   = threadIdx.x;
    const int ebase = blockIdx.x * TILE_E;
    const int eg    = tid & 3;      // edge group: edges eg*8 .. eg*8+7
    const int hg    = tid >> 2;     // col group: cols hg*4 .. hg*4+3  (hg in [0,96))

    // Phase 0: edge metadata + zero score accumulators
    if (tid < TILE_E) {
        int s = 0, d = 0;
        float bv = 0.f;
        int ge = ebase + tid;
        if (ge < E) {
            s  = edge[2 * ge + 0];
            d  = edge[2 * ge + 1];
            bv = (float)(mask[s] * mask[d]);
        }
        M->srcs[tid]  = s;
        M->dsts[tid]  = d;
        M->bothv[tid] = bv;
    }
    if (tid < 3 * TILE_E) ((float*)M->scores)[tid] = 0.f;
    __syncthreads();

    // Phase 1: gather node rows + form products into S[k][e] (k-major).
    // 896 = 28*32 so each warp stays inside one edge row -> coalesced loads.
    for (int idx = tid; idx < TILE_E * KTOT; idx += THREADS) {
        int e = idx / KTOT;
        int k = idx - e * KTOT;
        int s = M->srcs[e], d = M->dsts[e];
        float v;
        if (k < 128) v = z[s * 128 + k] * z[d * 128 + k];
        else {
            int kk = k - 128;
            v = chem[s * 768 + kk] * chem[d * 768 + kk];
        }
        S[k * ROWPAD + e] = v;
    }
    __syncthreads();

    // Phase 2: register-tiled GEMM: acc[ep][c] over 8 edges x 4 cols.
    unsigned long long acc[4][4];
    #pragma unroll
    for (int a = 0; a < 4; a++)
        #pragma unroll
        for (int b = 0; b < 4; b++) acc[a][b] = 0ull;

    const float* Wp = g_W + hg * 4;
    const float* Sp = S + eg * 8;

    #pragma unroll 2
    for (int k = 0; k < KTOT; k++) {
        float4 p0 = *reinterpret_cast<const float4*>(Sp + k * ROWPAD);
        float4 p1 = *reinterpret_cast<const float4*>(Sp + k * ROWPAD + 4);
        float4 w  = *reinterpret_cast<const float4*>(Wp + k * HTOT);

        unsigned long long P[4] = { pk2(p0.x, p0.y), pk2(p0.z, p0.w),
                                    pk2(p1.x, p1.y), pk2(p1.z, p1.w) };
        unsigned long long W2[4] = { pk2(w.x, w.x), pk2(w.y, w.y),
                                     pk2(w.z, w.z), pk2(w.w, w.w) };
        #pragma unroll
        for (int ep = 0; ep < 4; ep++)
            #pragma unroll
            for (int c = 0; c < 4; c++)
                fma2(acc[ep][c], P[ep], W2[c]);
    }

    // Phase 3: epilogue — bias, ReLU, second-layer weight, per-path reduce.
    {
        int col0 = hg * 4;
        int path = (col0 < 64) ? 0 : (col0 < 256) ? 1 : 2;  // 4 | path boundaries
        float bv[4], wv[4];
        #pragma unroll
        for (int c = 0; c < 4; c++) { bv[c] = g_b1[col0 + c]; wv[c] = g_w2[col0 + c]; }

        float psum[8];
        #pragma unroll
        for (int i = 0; i < 8; i++) psum[i] = 0.f;

        #pragma unroll
        for (int ep = 0; ep < 4; ep++)
            #pragma unroll
            for (int c = 0; c < 4; c++) {
                float2 p = upk2(acc[ep][c]);
                psum[2 * ep]     += fmaxf(p.x + bv[c], 0.f) * wv[c];
                psum[2 * ep + 1] += fmaxf(p.y + bv[c], 0.f) * wv[c];
            }

        #pragma unroll
        for (int i = 0; i < 8; i++)
            atomicAdd(&M->scores[path][eg * 8 + i], psum[i]);
    }
    __syncthreads();

    // Phase 4: softmax combine + mask select
    if (tid < TILE_E && ebase + tid < E) {
        float p0 = pw[0], p1 = pw[1], p2 = pw[2];
        float mx = fmaxf(p0, fmaxf(p1, p2));
        float e0 = expf(p0 - mx), e1 = expf(p1 - mx), e2 = expf(p2 - mx);
        float inv = 1.f / (e0 + e1 + e2);

        float ss  = M->scores[0][tid] + sb2[0];
        float sc  = M->scores[1][tid] + cb2[0];
        float sm  = M->scores[2][tid] + mb2[0];
        float combined = (e0 * ss + e1 * sc + e2 * sm) * inv;
        out[ebase + tid] = (M->bothv[tid] > 0.5f) ? combined : ss;
    }
}

extern "C" void kernel_launch(void* const* d_in, const int* in_sizes, int n_in,
                              void* d_out, int out_size)
{
    const float* z    = (const float*)d_in[0];
    const float* chem = (const float*)d_in[1];
    const int*   edge = (const int*)d_in[2];    // int32 pairs
    const int*   mask = (const int*)d_in[3];
    const float* sw1  = (const float*)d_in[4];
    const float* sb1  = (const float*)d_in[5];
    const float* sw2  = (const float*)d_in[6];
    const float* sb2  = (const float*)d_in[7];
    const float* cw1  = (const float*)d_in[8];
    const float* cb1  = (const float*)d_in[9];
    const float* cw2  = (const float*)d_in[10];
    const float* cb2  = (const float*)d_in[11];
    const float* mw1  = (const float*)d_in[12];
    const float* mb1  = (const float*)d_in[13];
    const float* mw2  = (const float*)d_in[14];
    const float* mb2  = (const float*)d_in[15];
    const float* pw   = (const float*)d_in[16];
    float*       out  = (float*)d_out;

    const int E = in_sizes[2] / 2;

    // Build packed weights (deterministic, every launch).
    {
        int total = KTOT * HTOT + HTOT;
        pack_kernel<<<(total + 255) / 256, 256>>>(sw1, sb1, sw2,
                                                  cw1, cb1, cw2,
                                                  mw1, mb1, mw2);
    }

    const int smem = KTOT * ROWPAD * 4 + (int)sizeof(Meta);
    cudaFuncSetAttribute(decoder_kernel,
                         cudaFuncAttributeMaxDynamicSharedMemorySize, smem);
    const int nblocks = (E + TILE_E - 1) / TILE_E;
    decoder_kernel<<<nblocks, THREADS, smem>>>(
        z, chem, edge, mask, sb2, cb2, mb2, pw, out, E);
}

// round 4
// speedup vs baseline: 5.2185x; 5.2185x over previous
#include <cuda_runtime.h>
#include <cuda_bf16.h>
#include <cstdint>

#define THREADS 256
#define TILE_E  64              // M per CTA
#define KTOT    896
#define HTOT    384
#define KC      64              // K per chunk
#define NCH     14              // 896/64
#define NWARP_N 4               // warps along N
#define NB_PER_W 12             // 8-col blocks per warp (96 cols)

// ---------- packed weights (built per launch) ----------
// Fragment-order bf16: index = (((c*48 + nb)*4 + ks)*32 + lane)*4 + reg*2 + pair
__device__ __align__(16) __nv_bfloat16 g_Bp_hi[KTOT * HTOT];
__device__ __align__(16) __nv_bfloat16 g_Bp_lo[KTOT * HTOT];
__device__ float g_b1[HTOT];
__device__ float g_w2[HTOT];

__global__ void pack_kernel(
    const float* __restrict__ sw1, const float* __restrict__ sb1, const float* __restrict__ sw2,
    const float* __restrict__ cw1, const float* __restrict__ cb1, const float* __restrict__ cw2,
    const float* __restrict__ mw1, const float* __restrict__ mb1, const float* __restrict__ mw2)
{
    int idx = blockIdx.x * blockDim.x + threadIdx.x;
    if (idx < KTOT * HTOT) {
        int k = idx / HTOT;
        int j = idx - k * HTOT;
        float v = 0.f;
        if (j < 64) {
            if (k < 128) v = sw1[k * 64 + j];
        } else if (j < 256) {
            if (k >= 128) v = cw1[(k - 128) * 192 + (j - 64)];
        } else {
            v = mw1[k * 128 + (j - 256)];
        }
        __nv_bfloat16 vh = __float2bfloat16(v);
        __nv_bfloat16 vl = __float2bfloat16(v - __bfloat162float(vh));
        // fragment-order destination
        int c  = k >> 6;          // chunk
        int kk = k & 63;
        int ks = kk >> 4;         // k16 step
        int kr = kk & 15;
        int nb = j >> 3;          // 8-col block (global, 0..47)
        int nr = j & 7;
        int lane = nr * 4 + ((kr & 7) >> 1);
        int reg  = kr >> 3;       // b0 / b1
        int pair = kr & 1;
        uint32_t off = ((((uint32_t)(c * 48 + nb) * 4 + ks) * 32 + lane) * 4) + reg * 2 + pair;
        g_Bp_hi[off] = vh;
        g_Bp_lo[off] = vl;
    } else if (idx < KTOT * HTOT + HTOT) {
        int j = idx - KTOT * HTOT;
        float b, w;
        if (j < 64)       { b = sb1[j];       w = sw2[j]; }
        else if (j < 256) { b = cb1[j - 64];  w = cw2[j - 64]; }
        else              { b = mb1[j - 256]; w = mw2[j - 256]; }
        g_b1[j] = b;
        g_w2[j] = w;
    }
}

// ---------- mma.sync helper (baseline PTX, runs as HMMA on sm_103) ----------
__device__ __forceinline__ void mma16816(float* d, const uint32_t* a, const uint32_t b0, const uint32_t b1) {
    asm volatile(
        "mma.sync.aligned.m16n8k16.row.col.f32.bf16.bf16.f32 "
        "{%0,%1,%2,%3}, {%4,%5,%6,%7}, {%8,%9}, {%0,%1,%2,%3};"
        : "+f"(d[0]), "+f"(d[1]), "+f"(d[2]), "+f"(d[3])
        : "r"(a[0]), "r"(a[1]), "r"(a[2]), "r"(a[3]), "r"(b0), "r"(b1));
}

__device__ __forceinline__ uint32_t pack_bf16x2(float x, float y) {
    __nv_bfloat162 h = __floats2bfloat162_rn(x, y);
    return *reinterpret_cast<uint32_t*>(&h);
}

// A smem: per dbuf, per split, 16 blocks (fm 0..3 x ks 0..3) of 512B, stride 528 (bank spread)
#define ABLK 528
#define AREG (16 * ABLK)        // 8448 B per split

__global__ void __launch_bounds__(THREADS, 1)
decoder_kernel(
    const float* __restrict__ z, const float* __restrict__ chem,
    const int*   __restrict__ edge, const int* __restrict__ mask,
    const float* __restrict__ sb2, const float* __restrict__ cb2,
    const float* __restrict__ mb2, const float* __restrict__ pw,
    float* __restrict__ out, int E)
{
    __shared__ __align__(16) char Asm[2][2][AREG];   // [dbuf][split hi/lo]
    __shared__ float red[NWARP_N][3][TILE_E];
    __shared__ int   Ssrc[TILE_E], Sdst[TILE_E];
    __shared__ float Sbv[TILE_E];

    const int tid  = threadIdx.x;
    const int wid  = tid >> 5;
    const int lane = tid & 31;
    const int nw   = wid & 3;          // n-warp (96 cols)
    const int mw   = wid >> 2;         // m-warp (32 rows)
    const int ebase = blockIdx.x * TILE_E;

    // ---- metadata + zero reduction buffer ----
    if (tid < TILE_E) {
        int ge = ebase + tid;
        int s = 0, d = 0;
        float bv = 0.f;
        if (ge < E) {
            s  = edge[2 * ge + 0];
            d  = edge[2 * ge + 1];
            bv = (float)(mask[s] * mask[d]);
        }
        Ssrc[tid] = s; Sdst[tid] = d; Sbv[tid] = bv;
    }
    for (int i = tid; i < NWARP_N * 3 * TILE_E; i += THREADS)
        ((float*)red)[i] = 0.f;
    __syncthreads();

    // ---- gather thread mapping: e = tid/4 (row), kq = tid%4 (k16 block) ----
    const int ge_  = tid >> 2;         // edge row 0..63
    const int kq   = tid & 3;
    const int r    = ge_ & 15;
    const int fm   = ge_ >> 4;
    const uint32_t abase = (uint32_t)(fm * 4 + kq) * ABLK + (r & 7) * 64 + (r >> 3) * 4;
    const int srow = Ssrc[ge_];
    const int drow = Sdst[ge_];

    float4 ga[4], gb[4];
    // prologue: gather chunk 0 (z, kb = 0)
    {
        const float* sp = z + (size_t)srow * 128 + kq * 16;
        const float* dp = z + (size_t)drow * 128 + kq * 16;
        #pragma unroll
        for (int i = 0; i < 4; i++) {
            ga[i] = *(const float4*)(sp + i * 4);
            gb[i] = *(const float4*)(dp + i * 4);
        }
    }

    // accumulators: [fm2][nb][4]
    float acc[2][NB_PER_W][4];
    #pragma unroll
    for (int a = 0; a < 2; a++)
        #pragma unroll
        for (int b = 0; b < NB_PER_W; b++)
            #pragma unroll
            for (int q = 0; q < 4; q++) acc[a][b][q] = 0.f;

    const uint2* __restrict__ Bhi = (const uint2*)g_Bp_hi;
    const uint2* __restrict__ Blo = (const uint2*)g_Bp_lo;

    #pragma unroll 1
    for (int c = 0; c < NCH; c++) {
        // ---- stage chunk c: split to bf16 hi/lo, store in fragment order ----
        {
            char* ah = Asm[c & 1][0];
            char* al = Asm[c & 1][1];
            #pragma unroll
            for (int i = 0; i < 4; i++) {
                float p0 = ga[i].x * gb[i].x;
                float p1 = ga[i].y * gb[i].y;
                float p2 = ga[i].z * gb[i].z;
                float p3 = ga[i].w * gb[i].w;
                __nv_bfloat16 h0 = __float2bfloat16(p0), h1 = __float2bfloat16(p1);
                __nv_bfloat16 h2 = __float2bfloat16(p2), h3 = __float2bfloat16(p3);
                float l0 = p0 - __bfloat162float(h0);
                float l1 = p1 - __bfloat162float(h1);
                float l2 = p2 - __bfloat162float(h2);
                float l3 = p3 - __bfloat162float(h3);
                uint32_t hi01 = ((uint32_t)__bfloat16_as_ushort(h0)) | ((uint32_t)__bfloat16_as_ushort(h1) << 16);
                uint32_t hi23 = ((uint32_t)__bfloat16_as_ushort(h2)) | ((uint32_t)__bfloat16_as_ushort(h3) << 16);
                uint32_t lo01 = pack_bf16x2(l0, l1);
                uint32_t lo23 = pack_bf16x2(l2, l3);
                uint32_t a0 = abase + (uint32_t)(((2 * i + 0) & 3) * 16 + (i >> 1) * 8);
                uint32_t a1 = abase + (uint32_t)(((2 * i + 1) & 3) * 16 + (i >> 1) * 8);
                *(uint32_t*)(ah + a0) = hi01;
                *(uint32_t*)(ah + a1) = hi23;
                *(uint32_t*)(al + a0) = lo01;
                *(uint32_t*)(al + a1) = lo23;
            }
        }
        __syncthreads();

        // ---- prefetch gather for chunk c+1 (latency hidden under MMA) ----
        if (c + 1 < NCH) {
            int cn = c + 1;
            const float* basep = (cn < 2) ? z : chem;
            int ldr = (cn < 2) ? 128 : 768;
            int kb  = (cn < 2) ? cn * 64 : (cn - 2) * 64;
            const float* sp = basep + (size_t)srow * ldr + kb + kq * 16;
            const float* dp = basep + (size_t)drow * ldr + kb + kq * 16;
            #pragma unroll
            for (int i = 0; i < 4; i++) {
                ga[i] = *(const float4*)(sp + i * 4);
                gb[i] = *(const float4*)(dp + i * 4);
            }
        }

        // ---- MMA: 4 k-steps x (12 nb x 2 fm x 3 split-terms) ----
        {
            const char* ah = Asm[c & 1][0];
            const char* al = Asm[c & 1][1];
            #pragma unroll
            for (int ks = 0; ks < 4; ks++) {
                uint32_t afh[2][4], afl[2][4];
                #pragma unroll
                for (int f = 0; f < 2; f++) {
                    uint32_t boff = (uint32_t)((mw * 2 + f) * 4 + ks) * ABLK + lane * 16;
                    uint4 vh = *(const uint4*)(ah + boff);
                    uint4 vl = *(const uint4*)(al + boff);
                    afh[f][0] = vh.x; afh[f][1] = vh.y; afh[f][2] = vh.z; afh[f][3] = vh.w;
                    afl[f][0] = vl.x; afl[f][1] = vl.y; afl[f][2] = vl.z; afl[f][3] = vl.w;
                }
                #pragma unroll
                for (int nb = 0; nb < NB_PER_W; nb++) {
                    uint32_t bidx = (((uint32_t)(c * 48 + nw * NB_PER_W + nb) * 4 + ks) * 32 + lane);
                    uint2 bh = Bhi[bidx];
                    uint2 bl = Blo[bidx];
                    #pragma unroll
                    for (int f = 0; f < 2; f++) {
                        mma16816(acc[f][nb], afh[f], bh.x, bh.y);   // hi*hi
                        mma16816(acc[f][nb], afh[f], bl.x, bl.y);   // hi*lo
                        mma16816(acc[f][nb], afl[f], bh.x, bh.y);   // lo*hi
                    }
                }
            }
        }
        __syncthreads();
    }

    // ---- epilogue: bias + ReLU + w2, per-path partials ----
    {
        const int qc = (lane & 3) * 2;
        float ps[4][3];
        #pragma unroll
        for (int s = 0; s < 4; s++)
            #pragma unroll
            for (int p = 0; p < 3; p++) ps[s][p] = 0.f;

        #pragma unroll
        for (int nb = 0; nb < NB_PER_W; nb++) {
            int col0 = nw * 96 + nb * 8;
            int p = (col0 < 64) ? 0 : (col0 < 256) ? 1 : 2;
            float bb0 = g_b1[col0 + qc],     bb1 = g_b1[col0 + qc + 1];
            float ww0 = g_w2[col0 + qc],     ww1 = g_w2[col0 + qc + 1];
            #pragma unroll
            for (int f = 0; f < 2; f++) {
                const float* a = acc[f][nb];
                ps[f * 2 + 0][p] += fmaxf(a[0] + bb0, 0.f) * ww0 + fmaxf(a[1] + bb1, 0.f) * ww1;
                ps[f * 2 + 1][p] += fmaxf(a[2] + bb0, 0.f) * ww0 + fmaxf(a[3] + bb1, 0.f) * ww1;
            }
        }
        // quad reduce (lanes sharing a row)
        #pragma unroll
        for (int s = 0; s < 4; s++)
            #pragma unroll
            for (int p = 0; p < 3; p++) {
                float v = ps[s][p];
                v += __shfl_xor_sync(0xffffffffu, v, 1);
                v += __shfl_xor_sync(0xffffffffu, v, 2);
                ps[s][p] = v;
            }
        if ((lane & 3) == 0) {
            #pragma unroll
            for (int f = 0; f < 2; f++)
                #pragma unroll
                for (int rr = 0; rr < 2; rr++) {
                    int el = (mw * 2 + f) * 16 + (lane >> 2) + rr * 8;
                    #pragma unroll
                    for (int p = 0; p < 3; p++)
                        red[nw][p][el] += ps[f * 2 + rr][p];   // exclusive (nw,el) slot
                }
        }
    }
    __syncthreads();

    if (tid < TILE_E && ebase + tid < E) {
        float s0 = 0.f, s1 = 0.f, s2 = 0.f;
        #pragma unroll
        for (int w = 0; w < NWARP_N; w++) {
            s0 += red[w][0][tid];
            s1 += red[w][1][tid];
            s2 += red[w][2][tid];
        }
        float p0 = pw[0], p1 = pw[1], p2 = pw[2];
        float mx = fmaxf(p0, fmaxf(p1, p2));
        float e0 = expf(p0 - mx), e1 = expf(p1 - mx), e2 = expf(p2 - mx);
        float inv = 1.f / (e0 + e1 + e2);
        float ss = s0 + sb2[0];
        float sc = s1 + cb2[0];
        float sm = s2 + mb2[0];
        float comb = (e0 * ss + e1 * sc + e2 * sm) * inv;
        out[ebase + tid] = (Sbv[tid] > 0.5f) ? comb : ss;
    }
}

extern "C" void kernel_launch(void* const* d_in, const int* in_sizes, int n_in,
                              void* d_out, int out_size)
{
    const float* z    = (const float*)d_in[0];
    const float* chem = (const float*)d_in[1];
    const int*   edge = (const int*)d_in[2];
    const int*   mask = (const int*)d_in[3];
    const float* sw1  = (const float*)d_in[4];
    const float* sb1  = (const float*)d_in[5];
    const float* sw2  = (const float*)d_in[6];
    const float* sb2  = (const float*)d_in[7];
    const float* cw1  = (const float*)d_in[8];
    const float* cb1  = (const float*)d_in[9];
    const float* cw2  = (const float*)d_in[10];
    const float* cb2  = (const float*)d_in[11];
    const float* mw1  = (const float*)d_in[12];
    const float* mb1  = (const float*)d_in[13];
    const float* mw2  = (const float*)d_in[14];
    const float* mb2  = (const float*)d_in[15];
    const float* pw   = (const float*)d_in[16];
    float*       out  = (float*)d_out;

    const int E = in_sizes[2] / 2;

    {
        int total = KTOT * HTOT + HTOT;
        pack_kernel<<<(total + 255) / 256, 256>>>(sw1, sb1, sw2,
                                                  cw1, cb1, cw2,
                                                  mw1, mb1, mw2);
    }

    const int nblocks = (E + TILE_E - 1) / TILE_E;
    decoder_kernel<<<nblocks, THREADS>>>(
        z, chem, edge, mask, sb2, cb2, mb2, pw, out, E);
}

// round 6
// speedup vs baseline: 5.3391x; 1.0231x over previous
#include <cuda_runtime.h>
#include <cuda_bf16.h>
#include <cstdint>

#define THREADS 512
#define TILE_E  64              // M per CTA
#define KTOT    896
#define HTOT    384
#define NCH     14              // 896/64
#define NWARP_N 8               // warps along N
#define NB_PER_W 6              // 8-col blocks per warp (48 cols)

// ---------- packed weights (built per launch) ----------
// Fragment-order bf16: index = (((c*48 + nb)*4 + ks)*32 + lane)*4 + reg*2 + pair
__device__ __align__(16) __nv_bfloat16 g_Bp_hi[KTOT * HTOT];
__device__ __align__(16) __nv_bfloat16 g_Bp_lo[KTOT * HTOT];
__device__ float g_b1[HTOT];
__device__ float g_w2[HTOT];

__global__ void pack_kernel(
    const float* __restrict__ sw1, const float* __restrict__ sb1, const float* __restrict__ sw2,
    const float* __restrict__ cw1, const float* __restrict__ cb1, const float* __restrict__ cw2,
    const float* __restrict__ mw1, const float* __restrict__ mb1, const float* __restrict__ mw2)
{
    int idx = blockIdx.x * blockDim.x + threadIdx.x;
    if (idx < KTOT * HTOT) {
        int k = idx / HTOT;
        int j = idx - k * HTOT;
        float v = 0.f;
        if (j < 64) {
            if (k < 128) v = sw1[k * 64 + j];
        } else if (j < 256) {
            if (k >= 128) v = cw1[(k - 128) * 192 + (j - 64)];
        } else {
            v = mw1[k * 128 + (j - 256)];
        }
        __nv_bfloat16 vh = __float2bfloat16(v);
        __nv_bfloat16 vl = __float2bfloat16(v - __bfloat162float(vh));
        int c  = k >> 6;          // chunk
        int kk = k & 63;
        int ks = kk >> 4;         // k16 step
        int kr = kk & 15;
        int nb = j >> 3;          // 8-col block (global, 0..47)
        int nr = j & 7;
        int lane = nr * 4 + ((kr & 7) >> 1);
        int reg  = kr >> 3;       // b0 / b1
        int pair = kr & 1;
        uint32_t off = ((((uint32_t)(c * 48 + nb) * 4 + ks) * 32 + lane) * 4) + reg * 2 + pair;
        g_Bp_hi[off] = vh;
        g_Bp_lo[off] = vl;
    } else if (idx < KTOT * HTOT + HTOT) {
        int j = idx - KTOT * HTOT;
        float b, w;
        if (j < 64)       { b = sb1[j];       w = sw2[j]; }
        else if (j < 256) { b = cb1[j - 64];  w = cw2[j - 64]; }
        else              { b = mb1[j - 256]; w = mw2[j - 256]; }
        g_b1[j] = b;
        g_w2[j] = w;
    }
}

// ---------- mma.sync helper (baseline PTX, legacy HMMA path on sm_103) ----------
__device__ __forceinline__ void mma16816(float* d, const uint32_t* a, const uint32_t b0, const uint32_t b1) {
    asm volatile(
        "mma.sync.aligned.m16n8k16.row.col.f32.bf16.bf16.f32 "
        "{%0,%1,%2,%3}, {%4,%5,%6,%7}, {%8,%9}, {%0,%1,%2,%3};"
        : "+f"(d[0]), "+f"(d[1]), "+f"(d[2]), "+f"(d[3])
        : "r"(a[0]), "r"(a[1]), "r"(a[2]), "r"(a[3]), "r"(b0), "r"(b1));
}

__device__ __forceinline__ uint32_t pack_bf16x2(float x, float y) {
    __nv_bfloat162 h = __floats2bfloat162_rn(x, y);
    return *reinterpret_cast<uint32_t*>(&h);
}

// A smem: per dbuf, per split, 16 blocks (fm 0..3 x ks 0..3) of 512B, stride 528
#define ABLK 528
#define AREG (16 * ABLK)

__global__ void __launch_bounds__(THREADS, 1)
decoder_kernel(
    const float* __restrict__ z, const float* __restrict__ chem,
    const int*   __restrict__ edge, const int* __restrict__ mask,
    const float* __restrict__ sb2, const float* __restrict__ cb2,
    const float* __restrict__ mb2, const float* __restrict__ pw,
    float* __restrict__ out, int E)
{
    __shared__ __align__(16) char Asm[2][2][AREG];   // [dbuf][split hi/lo]
    __shared__ float red[NWARP_N][3][TILE_E];
    __shared__ int   Ssrc[TILE_E], Sdst[TILE_E];
    __shared__ float Sbv[TILE_E];

    const int tid  = threadIdx.x;
    const int wid  = tid >> 5;
    const int lane = tid & 31;
    const int nw   = wid & 7;          // n-warp (48 cols)
    const int mw   = wid >> 3;         // m-warp (32 rows)
    const int ebase = blockIdx.x * TILE_E;

    // ---- metadata + zero reduction buffer ----
    if (tid < TILE_E) {
        int ge = ebase + tid;
        int s = 0, d = 0;
        float bv = 0.f;
        if (ge < E) {
            s  = edge[2 * ge + 0];
            d  = edge[2 * ge + 1];
            bv = (float)(mask[s] * mask[d]);
        }
        Ssrc[tid] = s; Sdst[tid] = d; Sbv[tid] = bv;
    }
    for (int i = tid; i < NWARP_N * 3 * TILE_E; i += THREADS)
        ((float*)red)[i] = 0.f;
    __syncthreads();

    // ---- gather mapping: e = tid/8 (row), q = tid%8 (8-k slice = 2 float4) ----
    const int ge_ = tid >> 3;          // edge row 0..63
    const int q   = tid & 7;
    const int r   = ge_ & 15;
    const int fm  = ge_ >> 4;
    // fragment block for this thread's k-slice: ks = q>>1
    const uint32_t abase = (uint32_t)(fm * 4 + (q >> 1)) * ABLK
                         + (uint32_t)((r & 7) * 64 + (r >> 3) * 4 + (q & 1) * 8);
    const int srow = Ssrc[ge_];
    const int drow = Sdst[ge_];

    float4 ga[2], gb[2];
    {   // prologue: gather chunk 0 (z, kb=0), k-range [8q, 8q+8)
        const float* sp = z + (size_t)srow * 128 + q * 8;
        const float* dp = z + (size_t)drow * 128 + q * 8;
        ga[0] = *(const float4*)(sp);     ga[1] = *(const float4*)(sp + 4);
        gb[0] = *(const float4*)(dp);     gb[1] = *(const float4*)(dp + 4);
    }

    // accumulators: [fm2][nb][4]
    float acc[2][NB_PER_W][4];
    #pragma unroll
    for (int a = 0; a < 2; a++)
        #pragma unroll
        for (int b = 0; b < NB_PER_W; b++)
            #pragma unroll
            for (int qq = 0; qq < 4; qq++) acc[a][b][qq] = 0.f;

    const uint2* __restrict__ Bhi = (const uint2*)g_Bp_hi;
    const uint2* __restrict__ Blo = (const uint2*)g_Bp_lo;

    #pragma unroll 1
    for (int c = 0; c < NCH; c++) {
        // ---- stage chunk c into buf[c&1] (split bf16 hi/lo, fragment order) ----
        {
            char* ah = Asm[c & 1][0];
            char* al = Asm[c & 1][1];
            #pragma unroll
            for (int i = 0; i < 2; i++) {
                float p0 = ga[i].x * gb[i].x;
                float p1 = ga[i].y * gb[i].y;
                float p2 = ga[i].z * gb[i].z;
                float p3 = ga[i].w * gb[i].w;
                __nv_bfloat16 h0 = __float2bfloat16(p0), h1 = __float2bfloat16(p1);
                __nv_bfloat16 h2 = __float2bfloat16(p2), h3 = __float2bfloat16(p3);
                float l0 = p0 - __bfloat162float(h0);
                float l1 = p1 - __bfloat162float(h1);
                float l2 = p2 - __bfloat162float(h2);
                float l3 = p3 - __bfloat162float(h3);
                uint32_t hi01 = ((uint32_t)__bfloat16_as_ushort(h0)) | ((uint32_t)__bfloat16_as_ushort(h1) << 16);
                uint32_t hi23 = ((uint32_t)__bfloat16_as_ushort(h2)) | ((uint32_t)__bfloat16_as_ushort(h3) << 16);
                uint32_t lo01 = pack_bf16x2(l0, l1);
                uint32_t lo23 = pack_bf16x2(l2, l3);
                uint32_t a0 = abase + (uint32_t)(i * 32);    // kpairs (4i, 4i+1)
                uint32_t a1 = a0 + 16;                       // kpairs (4i+2, 4i+3)
                *(uint32_t*)(ah + a0) = hi01;
                *(uint32_t*)(ah + a1) = hi23;
                *(uint32_t*)(al + a0) = lo01;
                *(uint32_t*)(al + a1) = lo23;
            }
        }
        __syncthreads();   // single barrier per chunk (see pipeline hazard analysis)

        // ---- prefetch gather for chunk c+1 ----
        if (c + 1 < NCH) {
            int cn = c + 1;
            const float* basep = (cn < 2) ? z : chem;
            int ldr = (cn < 2) ? 128 : 768;
            int kb  = (cn < 2) ? cn * 64 : (cn - 2) * 64;
            const float* sp = basep + (size_t)srow * ldr + kb + q * 8;
            const float* dp = basep + (size_t)drow * ldr + kb + q * 8;
            ga[0] = *(const float4*)(sp);     ga[1] = *(const float4*)(sp + 4);
            gb[0] = *(const float4*)(dp);     gb[1] = *(const float4*)(dp + 4);
        }

        // ---- MMA: 4 k-steps x (6 nb x 2 fm x 3 split-terms) ----
        {
            const char* ah = Asm[c & 1][0];
            const char* al = Asm[c & 1][1];
            #pragma unroll
            for (int ks = 0; ks < 4; ks++) {
                uint32_t afh[2][4], afl[2][4];
                #pragma unroll
                for (int f = 0; f < 2; f++) {
                    uint32_t boff = (uint32_t)((mw * 2 + f) * 4 + ks) * ABLK + lane * 16;
                    uint4 vh = *(const uint4*)(ah + boff);
                    uint4 vl = *(const uint4*)(al + boff);
                    afh[f][0] = vh.x; afh[f][1] = vh.y; afh[f][2] = vh.z; afh[f][3] = vh.w;
                    afl[f][0] = vl.x; afl[f][1] = vl.y; afl[f][2] = vl.z; afl[f][3] = vl.w;
                }
                #pragma unroll
                for (int nb = 0; nb < NB_PER_W; nb++) {
                    uint32_t bidx = (((uint32_t)(c * 48 + nw * NB_PER_W + nb) * 4 + ks) * 32 + lane);
                    uint2 bh = Bhi[bidx];
                    uint2 bl = Blo[bidx];
                    #pragma unroll
                    for (int f = 0; f < 2; f++) {
                        mma16816(acc[f][nb], afh[f], bh.x, bh.y);   // hi*hi
                        mma16816(acc[f][nb], afh[f], bl.x, bl.y);   // hi*lo
                        mma16816(acc[f][nb], afl[f], bh.x, bh.y);   // lo*hi
                    }
                }
            }
        }
    }
    __syncthreads();

    // ---- epilogue: bias + ReLU + w2, per-path partials ----
    {
        const int qc = (lane & 3) * 2;
        float ps[4][3];
        #pragma unroll
        for (int s = 0; s < 4; s++)
            #pragma unroll
            for (int p = 0; p < 3; p++) ps[s][p] = 0.f;

        #pragma unroll
        for (int nb = 0; nb < NB_PER_W; nb++) {
            int col0 = nw * 48 + nb * 8;
            int p = (col0 < 64) ? 0 : (col0 < 256) ? 1 : 2;   // 8 | boundaries
            float bb0 = g_b1[col0 + qc],     bb1 = g_b1[col0 + qc + 1];
            float ww0 = g_w2[col0 + qc],     ww1 = g_w2[col0 + qc + 1];
            #pragma unroll
            for (int f = 0; f < 2; f++) {
                const float* a = acc[f][nb];
                ps[f * 2 + 0][p] += fmaxf(a[0] + bb0, 0.f) * ww0 + fmaxf(a[1] + bb1, 0.f) * ww1;
                ps[f * 2 + 1][p] += fmaxf(a[2] + bb0, 0.f) * ww0 + fmaxf(a[3] + bb1, 0.f) * ww1;
            }
        }
        #pragma unroll
        for (int s = 0; s < 4; s++)
            #pragma unroll
            for (int p = 0; p < 3; p++) {
                float v = ps[s][p];
                v += __shfl_xor_sync(0xffffffffu, v, 1);
                v += __shfl_xor_sync(0xffffffffu, v, 2);
                ps[s][p] = v;
            }
        if ((lane & 3) == 0) {
            #pragma unroll
            for (int f = 0; f < 2; f++)
                #pragma unroll
                for (int rr = 0; rr < 2; rr++) {
                    int el = (mw * 2 + f) * 16 + (lane >> 2) + rr * 8;
                    #pragma unroll
                    for (int p = 0; p < 3; p++)
                        red[nw][p][el] += ps[f * 2 + rr][p];   // exclusive (nw,el) slot
                }
        }
    }
    __syncthreads();

    if (tid < TILE_E && ebase + tid < E) {
        float s0 = 0.f, s1 = 0.f, s2 = 0.f;
        #pragma unroll
        for (int w = 0; w < NWARP_N; w++) {
            s0 += red[w][0][tid];
            s1 += red[w][1][tid];
            s2 += red[w][2][tid];
        }
        float p0 = pw[0], p1 = pw[1], p2 = pw[2];
        float mx = fmaxf(p0, fmaxf(p1, p2));
        float e0 = expf(p0 - mx), e1 = expf(p1 - mx), e2 = expf(p2 - mx);
        float inv = 1.f / (e0 + e1 + e2);
        float ss = s0 + sb2[0];
        float sc = s1 + cb2[0];
        float sm = s2 + mb2[0];
        float comb = (e0 * ss + e1 * sc + e2 * sm) * inv;
        out[ebase + tid] = (Sbv[tid] > 0.5f) ? comb : ss;
    }
}

extern "C" void kernel_launch(void* const* d_in, const int* in_sizes, int n_in,
                              void* d_out, int out_size)
{
    const float* z    = (const float*)d_in[0];
    const float* chem = (const float*)d_in[1];
    const int*   edge = (const int*)d_in[2];
    const int*   mask = (const int*)d_in[3];
    const float* sw1  = (const float*)d_in[4];
    const float* sb1  = (const float*)d_in[5];
    const float* sw2  = (const float*)d_in[6];
    const float* sb2  = (const float*)d_in[7];
    const float* cw1  = (const float*)d_in[8];
    const float* cb1  = (const float*)d_in[9];
    const float* cw2  = (const float*)d_in[10];
    const float* cb2  = (const float*)d_in[11];
    const float* mw1  = (const float*)d_in[12];
    const float* mb1  = (const float*)d_in[13];
    const float* mw2  = (const float*)d_in[14];
    const float* mb2  = (const float*)d_in[15];
    const float* pw   = (const float*)d_in[16];
    float*       out  = (float*)d_out;

    const int E = in_sizes[2] / 2;

    {
        int total = KTOT * HTOT + HTOT;
        pack_kernel<<<(total + 255) / 256, 256>>>(sw1, sb1, sw2,
                                                  cw1, cb1, cw2,
                                                  mw1, mb1, mw2);
    }

    const int nblocks = (E + TILE_E - 1) / TILE_E;
    decoder_kernel<<<nblocks, THREADS>>>(
        z, chem, edge, mask, sb2, cb2, mb2, pw, out, E);
}